// round 7
// baseline (speedup 1.0000x reference)
#include <cuda_runtime.h>

// RoIAlign (FPN, 4 levels) + fused 2x2 stride-1 avg epilogue.
// Grid: 8 blocks per roi (channel slices of 32), 256 thr = 8 warps/block,
// each warp handles 4 channels, processed 2 at a time (ILP x2).
// Lane l (<28) owns x-tap column l = 2*t + k. Fast path (rh <= 14 px):
// each pooled row's 4 bilinear rows fit a 3-row window -> <=3 predicated
// loads per pooled row. Reduction: out[j,px] needs the sum of
// (val[j]+val[j+1])*wcol over the 8 contiguous lanes 4px..4px+7, which
// shfl_down 1,2,4 computes directly (overlapping windows OK) -> 18 SHFL
// per channel instead of 20, no intermediate arrays.

namespace {
constexpr int C = 256;

__global__ __launch_bounds__(256, 4)
void roialign_kernel(const float* __restrict__ f0, const float* __restrict__ f1,
                     const float* __restrict__ f2, const float* __restrict__ f3,
                     const float* __restrict__ rois, float* __restrict__ out)
{
    const int roi   = blockIdx.x >> 3;
    const int slice = blockIdx.x & 7;       // 32-channel slice
    const int b = roi >> 9;                 // N = 512
    const float* r = rois + roi * 7;

    __shared__ int    scol[32];             // column index per lane (clamped)
    __shared__ float  swx[32];              // x-weight per lane (0 if invalid)
    __shared__ float4 sy[14];               // {off0, off1 (int bits), wy0, wy1}
    __shared__ float4 spy[7];               // fast: {baseOff bits, w0, w1, w2}

    const int tid = threadIdx.x;
    const int lev = (int)r[6];
    const int Wd = 160 >> lev;
    const float scale = 8.0f / (float)(1 << lev);

    // uniform fast-path condition: sample stride rh/14 <= 1
    const float rh_u = fmaxf((r[4] - r[2]) * scale, 1.0f);
    const bool fast = (rh_u <= 14.0f);

    if (tid < 32) {                         // x-tap setup: lane l = 2*t + k
        int l = min(tid, 27);               // idle lanes alias lane 27
        int t = l >> 1, k = l & 1;
        const float c1 = r[1] * scale;
        const float c2 = r[3] * scale;
        const float bin = fmaxf(c2 - c1, 1.0f) * (1.0f / 7.0f);
        const float off = (float)(t >> 1) + ((t & 1) ? 0.75f : 0.25f);
        const float pos = c1 + off * bin;
        const bool valid = (pos >= -1.0f) && (pos <= (float)Wd);
        const float p = fminf(fmaxf(pos, 0.0f), (float)(Wd - 1));
        const float p0 = floorf(p);
        const int i0 = (int)p0;
        const int i1 = min(i0 + 1, Wd - 1);
        const float lx = p - p0;
        scol[tid] = k ? i1 : i0;
        // fold the 2x2-avg-pool scale (1/16) into the x weight
        swx[tid] = (tid < 28 && valid) ? 0.0625f * (k ? lx : 1.0f - lx) : 0.0f;
    } else if (tid < 46) {                  // y-sample setup: s = tid - 32
        const int s = tid - 32;
        const float c1 = r[2] * scale;
        const float c2 = r[4] * scale;
        const float bin = fmaxf(c2 - c1, 1.0f) * (1.0f / 7.0f);
        const float off = (float)(s >> 1) + ((s & 1) ? 0.75f : 0.25f);
        const float pos = c1 + off * bin;
        const bool valid = (pos >= -1.0f) && (pos <= (float)Wd);
        const float p = fminf(fmaxf(pos, 0.0f), (float)(Wd - 1));
        const float p0 = floorf(p);
        const int i0 = (int)p0;
        const int i1 = min(i0 + 1, Wd - 1);
        const float ly = p - p0;
        float4 v;
        v.x = __int_as_float(i0 * Wd);
        v.y = __int_as_float(i1 * Wd);
        v.z = valid ? (1.0f - ly) : 0.0f;
        v.w = valid ? ly : 0.0f;
        sy[s] = v;
    } else if (tid < 53 && fast) {          // fast-path 3-row windows, py = tid-46
        const int py = tid - 46;
        const float c1 = r[2] * scale;
        const float c2 = r[4] * scale;
        const float bin = fmaxf(c2 - c1, 1.0f) * (1.0f / 7.0f);
        float w[3] = {0.0f, 0.0f, 0.0f};
        int base = 0;
        #pragma unroll
        for (int h = 0; h < 2; ++h) {
            const int s = 2 * py + h;
            const float off = (float)(s >> 1) + ((s & 1) ? 0.75f : 0.25f);
            const float pos = c1 + off * bin;
            const bool valid = (pos >= -1.0f) && (pos <= (float)Wd);
            const float p = fminf(fmaxf(pos, 0.0f), (float)(Wd - 1));
            const float p0 = floorf(p);
            const int i0 = (int)p0;
            const int i1 = min(i0 + 1, Wd - 1);
            const float ly = p - p0;
            if (h == 0) base = i0;          // rows monotone within the bin
            w[i0 - base] += valid ? (1.0f - ly) : 0.0f;
            w[i1 - base] += valid ? ly : 0.0f;
        }
        float4 e;
        e.x = __int_as_float(base * Wd);
        e.y = w[0]; e.z = w[1]; e.w = w[2];
        spy[py] = e;
    }
    __syncthreads();

    const float* fb = (lev == 0) ? f0 : (lev == 1) ? f1 : (lev == 2) ? f2 : f3;
    const int HW = Wd * Wd;
    const int warp = tid >> 5;
    const int lane = tid & 31;

    const int mycol = scol[lane];
    const float wcol = swx[lane];
    float* outroi = out + (size_t)roi * (C * 36);
    const int cbase = slice * 32 + warp * 4;

    #pragma unroll 1
    for (int i = 0; i < 4; i += 2) {
        const int c0 = cbase + i;
        const float* fcA = fb + (size_t)(b * C + c0) * HW + mycol;
        const float* fcB = fcA + HW;

        float valA[7], valB[7];
        if (fast) {
            #pragma unroll
            for (int py = 0; py < 7; ++py) {
                const float4 e = spy[py];
                const int bo = __float_as_int(e.x);
                float a = 0.0f, bb = 0.0f;
                if (e.y != 0.0f) { a += e.y * __ldg(fcA + bo);
                                   bb += e.y * __ldg(fcB + bo); }
                if (e.z != 0.0f) { a += e.z * __ldg(fcA + bo + Wd);
                                   bb += e.z * __ldg(fcB + bo + Wd); }
                if (e.w != 0.0f) { a += e.w * __ldg(fcA + bo + 2 * Wd);
                                   bb += e.w * __ldg(fcB + bo + 2 * Wd); }
                valA[py] = a;
                valB[py] = bb;
            }
        } else {
            #pragma unroll
            for (int py = 0; py < 7; ++py) { valA[py] = 0.0f; valB[py] = 0.0f; }
            #pragma unroll
            for (int s = 0; s < 14; ++s) {
                const float4 yv = sy[s];
                const int o0 = __float_as_int(yv.x);
                const int o1 = __float_as_int(yv.y);
                const float a0 = __ldg(fcA + o0);
                const float a1 = __ldg(fcA + o1);
                const float b0 = __ldg(fcB + o0);
                const float b1 = __ldg(fcB + o1);
                valA[s >> 1] += yv.z * a0 + yv.w * a1;
                valB[s >> 1] += yv.z * b0 + yv.w * b1;
            }
        }

        // out[j, px] = sum over lanes 4px..4px+7 of (val[j]+val[j+1])*wcol.
        // shfl_down 1,2,4 yields the contiguous 8-lane window sum at lane 4px.
        float uA[6], uB[6];
        #pragma unroll
        for (int j = 0; j < 6; ++j) {
            uA[j] = (valA[j] + valA[j + 1]) * wcol;
            uB[j] = (valB[j] + valB[j + 1]) * wcol;
        }
        #pragma unroll
        for (int j = 0; j < 6; ++j) {
            uA[j] += __shfl_down_sync(0xFFFFFFFFu, uA[j], 1);
            uB[j] += __shfl_down_sync(0xFFFFFFFFu, uB[j], 1);
            uA[j] += __shfl_down_sync(0xFFFFFFFFu, uA[j], 2);
            uB[j] += __shfl_down_sync(0xFFFFFFFFu, uB[j], 2);
            uA[j] += __shfl_down_sync(0xFFFFFFFFu, uA[j], 4);
            uB[j] += __shfl_down_sync(0xFFFFFFFFu, uB[j], 4);
        }

        if ((lane & 3) == 0 && lane < 24) {
            const int px = lane >> 2;       // 0..5
            float* opA = outroi + c0 * 36 + px;
            #pragma unroll
            for (int j = 0; j < 6; ++j) {
                opA[j * 6]      = uA[j];
                opA[36 + j * 6] = uB[j];
            }
        }
    }
}
} // namespace

extern "C" void kernel_launch(void* const* d_in, const int* in_sizes, int n_in,
                              void* d_out, int out_size) {
    const float* f0   = (const float*)d_in[0];
    const float* f1   = (const float*)d_in[1];
    const float* f2   = (const float*)d_in[2];
    const float* f3   = (const float*)d_in[3];
    const float* rois = (const float*)d_in[4];
    const int nroi = in_sizes[4] / 7;       // B*N = 1024
    roialign_kernel<<<nroi * 8, 256>>>(f0, f1, f2, f3, rois, (float*)d_out);
}

// round 8
// speedup vs baseline: 1.6257x; 1.6257x over previous
#include <cuda_runtime.h>

// RoIAlign (FPN, 4 levels) + fused 2x2 stride-1 avg epilogue.
// Grid: 4 blocks per roi (channel slices of 64), 256 thr = 8 warps/block,
// each warp handles 8 channels, processed 2 at a time (ILP x2).
// Lane l (<28) owns x-tap column l = 2*t + k. Fast path (rh <= 14 px):
// each pooled row's 4 bilinear rows fit a 3-row window -> <=3 predicated
// loads per pooled row. Reduction: out[j,px] needs the sum of
// (val[j]+val[j+1])*wcol over the 8 contiguous lanes 4px..4px+7, which
// shfl_down 1,2,4 computes directly (overlapping windows OK) -> 18 SHFL
// per channel, no intermediate arrays. Single setup barrier.

namespace {
constexpr int C = 256;

__global__ __launch_bounds__(256, 4)
void roialign_kernel(const float* __restrict__ f0, const float* __restrict__ f1,
                     const float* __restrict__ f2, const float* __restrict__ f3,
                     const float* __restrict__ rois, float* __restrict__ out)
{
    const int roi   = blockIdx.x >> 2;
    const int slice = blockIdx.x & 3;       // 64-channel slice
    const int b = roi >> 9;                 // N = 512
    const float* r = rois + roi * 7;

    __shared__ int    scol[32];             // column index per lane (clamped)
    __shared__ float  swx[32];              // x-weight per lane (0 if invalid)
    __shared__ float4 sy[14];               // {off0, off1 (int bits), wy0, wy1}
    __shared__ float4 spy[7];               // fast: {baseOff bits, w0, w1, w2}

    const int tid = threadIdx.x;
    const int lev = (int)r[6];
    const int Wd = 160 >> lev;
    const float scale = 8.0f / (float)(1 << lev);

    // uniform fast-path condition: sample stride rh/14 <= 1
    const float rh_u = fmaxf((r[4] - r[2]) * scale, 1.0f);
    const bool fast = (rh_u <= 14.0f);

    if (tid < 32) {                         // x-tap setup: lane l = 2*t + k
        int l = min(tid, 27);               // idle lanes alias lane 27
        int t = l >> 1, k = l & 1;
        const float c1 = r[1] * scale;
        const float c2 = r[3] * scale;
        const float bin = fmaxf(c2 - c1, 1.0f) * (1.0f / 7.0f);
        const float off = (float)(t >> 1) + ((t & 1) ? 0.75f : 0.25f);
        const float pos = c1 + off * bin;
        const bool valid = (pos >= -1.0f) && (pos <= (float)Wd);
        const float p = fminf(fmaxf(pos, 0.0f), (float)(Wd - 1));
        const float p0 = floorf(p);
        const int i0 = (int)p0;
        const int i1 = min(i0 + 1, Wd - 1);
        const float lx = p - p0;
        scol[tid] = k ? i1 : i0;
        // fold the 2x2-avg-pool scale (1/16) into the x weight
        swx[tid] = (tid < 28 && valid) ? 0.0625f * (k ? lx : 1.0f - lx) : 0.0f;
    } else if (tid < 46) {                  // y-sample setup: s = tid - 32
        const int s = tid - 32;
        const float c1 = r[2] * scale;
        const float c2 = r[4] * scale;
        const float bin = fmaxf(c2 - c1, 1.0f) * (1.0f / 7.0f);
        const float off = (float)(s >> 1) + ((s & 1) ? 0.75f : 0.25f);
        const float pos = c1 + off * bin;
        const bool valid = (pos >= -1.0f) && (pos <= (float)Wd);
        const float p = fminf(fmaxf(pos, 0.0f), (float)(Wd - 1));
        const float p0 = floorf(p);
        const int i0 = (int)p0;
        const int i1 = min(i0 + 1, Wd - 1);
        const float ly = p - p0;
        float4 v;
        v.x = __int_as_float(i0 * Wd);
        v.y = __int_as_float(i1 * Wd);
        v.z = valid ? (1.0f - ly) : 0.0f;
        v.w = valid ? ly : 0.0f;
        sy[s] = v;
    } else if (tid < 53 && fast) {          // fast-path 3-row windows, py = tid-46
        const int py = tid - 46;
        const float c1 = r[2] * scale;
        const float c2 = r[4] * scale;
        const float bin = fmaxf(c2 - c1, 1.0f) * (1.0f / 7.0f);
        float w[3] = {0.0f, 0.0f, 0.0f};
        int base = 0;
        #pragma unroll
        for (int h = 0; h < 2; ++h) {
            const int s = 2 * py + h;
            const float off = (float)(s >> 1) + ((s & 1) ? 0.75f : 0.25f);
            const float pos = c1 + off * bin;
            const bool valid = (pos >= -1.0f) && (pos <= (float)Wd);
            const float p = fminf(fmaxf(pos, 0.0f), (float)(Wd - 1));
            const float p0 = floorf(p);
            const int i0 = (int)p0;
            const int i1 = min(i0 + 1, Wd - 1);
            const float ly = p - p0;
            if (h == 0) base = i0;          // rows monotone within the bin
            w[i0 - base] += valid ? (1.0f - ly) : 0.0f;
            w[i1 - base] += valid ? ly : 0.0f;
        }
        float4 e;
        e.x = __int_as_float(base * Wd);
        e.y = w[0]; e.z = w[1]; e.w = w[2];
        spy[py] = e;
    }
    __syncthreads();

    const float* fb = (lev == 0) ? f0 : (lev == 1) ? f1 : (lev == 2) ? f2 : f3;
    const int HW = Wd * Wd;
    const int warp = tid >> 5;
    const int lane = tid & 31;

    const int mycol = scol[lane];
    const float wcol = swx[lane];
    float* outroi = out + (size_t)roi * (C * 36);
    const int cbase = slice * 64 + warp * 8;

    #pragma unroll 1
    for (int i = 0; i < 8; i += 2) {
        const int c0 = cbase + i;
        const float* fcA = fb + (size_t)(b * C + c0) * HW + mycol;
        const float* fcB = fcA + HW;

        float valA[7], valB[7];
        if (fast) {
            #pragma unroll
            for (int py = 0; py < 7; ++py) {
                const float4 e = spy[py];
                const int bo = __float_as_int(e.x);
                float a = 0.0f, bb = 0.0f;
                if (e.y != 0.0f) { a += e.y * __ldg(fcA + bo);
                                   bb += e.y * __ldg(fcB + bo); }
                if (e.z != 0.0f) { a += e.z * __ldg(fcA + bo + Wd);
                                   bb += e.z * __ldg(fcB + bo + Wd); }
                if (e.w != 0.0f) { a += e.w * __ldg(fcA + bo + 2 * Wd);
                                   bb += e.w * __ldg(fcB + bo + 2 * Wd); }
                valA[py] = a;
                valB[py] = bb;
            }
        } else {
            #pragma unroll
            for (int py = 0; py < 7; ++py) { valA[py] = 0.0f; valB[py] = 0.0f; }
            #pragma unroll
            for (int s = 0; s < 14; ++s) {
                const float4 yv = sy[s];
                const int o0 = __float_as_int(yv.x);
                const int o1 = __float_as_int(yv.y);
                const float a0 = __ldg(fcA + o0);
                const float a1 = __ldg(fcA + o1);
                const float b0 = __ldg(fcB + o0);
                const float b1 = __ldg(fcB + o1);
                valA[s >> 1] += yv.z * a0 + yv.w * a1;
                valB[s >> 1] += yv.z * b0 + yv.w * b1;
            }
        }

        // out[j, px] = sum over lanes 4px..4px+7 of (val[j]+val[j+1])*wcol.
        // shfl_down 1,2,4 yields the contiguous 8-lane window sum at lane 4px.
        float uA[6], uB[6];
        #pragma unroll
        for (int j = 0; j < 6; ++j) {
            uA[j] = (valA[j] + valA[j + 1]) * wcol;
            uB[j] = (valB[j] + valB[j + 1]) * wcol;
        }
        #pragma unroll
        for (int j = 0; j < 6; ++j) {
            uA[j] += __shfl_down_sync(0xFFFFFFFFu, uA[j], 1);
            uB[j] += __shfl_down_sync(0xFFFFFFFFu, uB[j], 1);
            uA[j] += __shfl_down_sync(0xFFFFFFFFu, uA[j], 2);
            uB[j] += __shfl_down_sync(0xFFFFFFFFu, uB[j], 2);
            uA[j] += __shfl_down_sync(0xFFFFFFFFu, uA[j], 4);
            uB[j] += __shfl_down_sync(0xFFFFFFFFu, uB[j], 4);
        }

        if ((lane & 3) == 0 && lane < 24) {
            const int px = lane >> 2;       // 0..5
            float* opA = outroi + c0 * 36 + px;
            #pragma unroll
            for (int j = 0; j < 6; ++j) {
                opA[j * 6]      = uA[j];
                opA[36 + j * 6] = uB[j];
            }
        }
    }
}
} // namespace

extern "C" void kernel_launch(void* const* d_in, const int* in_sizes, int n_in,
                              void* d_out, int out_size) {
    const float* f0   = (const float*)d_in[0];
    const float* f1   = (const float*)d_in[1];
    const float* f2   = (const float*)d_in[2];
    const float* f3   = (const float*)d_in[3];
    const float* rois = (const float*)d_in[4];
    const int nroi = in_sizes[4] / 7;       // B*N = 1024
    roialign_kernel<<<nroi * 4, 256>>>(f0, f1, f2, f3, rois, (float*)d_out);
}

// round 9
// speedup vs baseline: 1.6569x; 1.0192x over previous
#include <cuda_runtime.h>

// RoIAlign (FPN, 4 levels) + fused 2x2 stride-1 avg epilogue.
// Grid: 4 blocks per roi (channel slices of 64), 256 thr = 8 warps/block,
// each warp handles 8 channels, processed 2 at a time (ILP x2).
// Lane l (<28) owns x-tap column l = 2*t + k. Fast path (rh <= 14 px):
// each pooled row's 4 bilinear rows fit a 3-row window -> <=3 predicated
// loads per pooled row. Streaming epilogue: bin-row py is consumed as soon
// as py-1/py exist (u=(v[py-1]+v[py])*wcol, 3-shfl 8-lane window sum,
// immediate store) so no val[7] arrays stay live -> fits 48 regs and
// 5 CTAs/SM for latency hiding.

namespace {
constexpr int C = 256;

__global__ __launch_bounds__(256, 5)
void roialign_kernel(const float* __restrict__ f0, const float* __restrict__ f1,
                     const float* __restrict__ f2, const float* __restrict__ f3,
                     const float* __restrict__ rois, float* __restrict__ out)
{
    const int roi   = blockIdx.x >> 2;
    const int slice = blockIdx.x & 3;       // 64-channel slice
    const int b = roi >> 9;                 // N = 512
    const float* r = rois + roi * 7;

    __shared__ int    scol[32];             // column index per lane (clamped)
    __shared__ float  swx[32];              // x-weight per lane (0 if invalid)
    __shared__ float4 sy[14];               // {off0, off1 (int bits), wy0, wy1}
    __shared__ float4 spy[7];               // fast: {baseOff bits, w0, w1, w2}

    const int tid = threadIdx.x;
    const int lev = (int)r[6];
    const int Wd = 160 >> lev;
    const float scale = 8.0f / (float)(1 << lev);

    // uniform fast-path condition: sample stride rh/14 <= 1
    const float rh_u = fmaxf((r[4] - r[2]) * scale, 1.0f);
    const bool fast = (rh_u <= 14.0f);

    if (tid < 32) {                         // x-tap setup: lane l = 2*t + k
        int l = min(tid, 27);               // idle lanes alias lane 27
        int t = l >> 1, k = l & 1;
        const float c1 = r[1] * scale;
        const float c2 = r[3] * scale;
        const float bin = fmaxf(c2 - c1, 1.0f) * (1.0f / 7.0f);
        const float off = (float)(t >> 1) + ((t & 1) ? 0.75f : 0.25f);
        const float pos = c1 + off * bin;
        const bool valid = (pos >= -1.0f) && (pos <= (float)Wd);
        const float p = fminf(fmaxf(pos, 0.0f), (float)(Wd - 1));
        const float p0 = floorf(p);
        const int i0 = (int)p0;
        const int i1 = min(i0 + 1, Wd - 1);
        const float lx = p - p0;
        scol[tid] = k ? i1 : i0;
        // fold the 2x2-avg-pool scale (1/16) into the x weight
        swx[tid] = (tid < 28 && valid) ? 0.0625f * (k ? lx : 1.0f - lx) : 0.0f;
    } else if (tid < 46) {                  // y-sample setup: s = tid - 32
        const int s = tid - 32;
        const float c1 = r[2] * scale;
        const float c2 = r[4] * scale;
        const float bin = fmaxf(c2 - c1, 1.0f) * (1.0f / 7.0f);
        const float off = (float)(s >> 1) + ((s & 1) ? 0.75f : 0.25f);
        const float pos = c1 + off * bin;
        const bool valid = (pos >= -1.0f) && (pos <= (float)Wd);
        const float p = fminf(fmaxf(pos, 0.0f), (float)(Wd - 1));
        const float p0 = floorf(p);
        const int i0 = (int)p0;
        const int i1 = min(i0 + 1, Wd - 1);
        const float ly = p - p0;
        float4 v;
        v.x = __int_as_float(i0 * Wd);
        v.y = __int_as_float(i1 * Wd);
        v.z = valid ? (1.0f - ly) : 0.0f;
        v.w = valid ? ly : 0.0f;
        sy[s] = v;
    } else if (tid < 53 && fast) {          // fast-path 3-row windows, py = tid-46
        const int py = tid - 46;
        const float c1 = r[2] * scale;
        const float c2 = r[4] * scale;
        const float bin = fmaxf(c2 - c1, 1.0f) * (1.0f / 7.0f);
        float w[3] = {0.0f, 0.0f, 0.0f};
        int base = 0;
        #pragma unroll
        for (int h = 0; h < 2; ++h) {
            const int s = 2 * py + h;
            const float off = (float)(s >> 1) + ((s & 1) ? 0.75f : 0.25f);
            const float pos = c1 + off * bin;
            const bool valid = (pos >= -1.0f) && (pos <= (float)Wd);
            const float p = fminf(fmaxf(pos, 0.0f), (float)(Wd - 1));
            const float p0 = floorf(p);
            const int i0 = (int)p0;
            const int i1 = min(i0 + 1, Wd - 1);
            const float ly = p - p0;
            if (h == 0) base = i0;          // rows monotone within the bin
            w[i0 - base] += valid ? (1.0f - ly) : 0.0f;
            w[i1 - base] += valid ? ly : 0.0f;
        }
        float4 e;
        e.x = __int_as_float(base * Wd);
        e.y = w[0]; e.z = w[1]; e.w = w[2];
        spy[py] = e;
    }
    __syncthreads();

    const float* fb = (lev == 0) ? f0 : (lev == 1) ? f1 : (lev == 2) ? f2 : f3;
    const int HW = Wd * Wd;
    const int warp = tid >> 5;
    const int lane = tid & 31;

    const int mycol = scol[lane];
    const float wcol = swx[lane];
    const bool active = (lane & 3) == 0 && lane < 24;
    const int px = lane >> 2;               // 0..5 when active
    float* outroi = out + (size_t)roi * (C * 36) + px;
    const int cbase = slice * 64 + warp * 8;

    #pragma unroll 1
    for (int i = 0; i < 8; i += 2) {
        const int c0 = cbase + i;
        const float* fcA = fb + (size_t)(b * C + c0) * HW + mycol;
        const float* fcB = fcA + HW;
        float* opA = outroi + c0 * 36;

        float prevA, prevB;
        #pragma unroll
        for (int py = 0; py < 7; ++py) {
            float vA, vB;
            if (fast) {
                const float4 e = spy[py];
                const int bo = __float_as_int(e.x);
                float a = 0.0f, bb = 0.0f;
                if (e.y != 0.0f) { a += e.y * __ldg(fcA + bo);
                                   bb += e.y * __ldg(fcB + bo); }
                if (e.z != 0.0f) { a += e.z * __ldg(fcA + bo + Wd);
                                   bb += e.z * __ldg(fcB + bo + Wd); }
                if (e.w != 0.0f) { a += e.w * __ldg(fcA + bo + 2 * Wd);
                                   bb += e.w * __ldg(fcB + bo + 2 * Wd); }
                vA = a; vB = bb;
            } else {
                const float4 y0 = sy[2 * py];
                const float4 y1 = sy[2 * py + 1];
                const int o00 = __float_as_int(y0.x);
                const int o01 = __float_as_int(y0.y);
                const int o10 = __float_as_int(y1.x);
                const int o11 = __float_as_int(y1.y);
                const float a00 = __ldg(fcA + o00);
                const float a01 = __ldg(fcA + o01);
                const float a10 = __ldg(fcA + o10);
                const float a11 = __ldg(fcA + o11);
                const float b00 = __ldg(fcB + o00);
                const float b01 = __ldg(fcB + o01);
                const float b10 = __ldg(fcB + o10);
                const float b11 = __ldg(fcB + o11);
                vA = y0.z * a00 + y0.w * a01 + y1.z * a10 + y1.w * a11;
                vB = y0.z * b00 + y0.w * b01 + y1.z * b10 + y1.w * b11;
            }
            if (py > 0) {
                // out[py-1, px] = sum over lanes 4px..4px+7 of
                // (v[py-1]+v[py])*wcol; shfl_down 1,2,4 builds the 8-lane
                // window sum at lane 4px (overlapping windows OK).
                float uA = (prevA + vA) * wcol;
                float uB = (prevB + vB) * wcol;
                uA += __shfl_down_sync(0xFFFFFFFFu, uA, 1);
                uB += __shfl_down_sync(0xFFFFFFFFu, uB, 1);
                uA += __shfl_down_sync(0xFFFFFFFFu, uA, 2);
                uB += __shfl_down_sync(0xFFFFFFFFu, uB, 2);
                uA += __shfl_down_sync(0xFFFFFFFFu, uA, 4);
                uB += __shfl_down_sync(0xFFFFFFFFu, uB, 4);
                if (active) {
                    opA[(py - 1) * 6]      = uA;
                    opA[36 + (py - 1) * 6] = uB;
                }
            }
            prevA = vA;
            prevB = vB;
        }
    }
}
} // namespace

extern "C" void kernel_launch(void* const* d_in, const int* in_sizes, int n_in,
                              void* d_out, int out_size) {
    const float* f0   = (const float*)d_in[0];
    const float* f1   = (const float*)d_in[1];
    const float* f2   = (const float*)d_in[2];
    const float* f3   = (const float*)d_in[3];
    const float* rois = (const float*)d_in[4];
    const int nroi = in_sizes[4] / 7;       // B*N = 1024
    roialign_kernel<<<nroi * 4, 256>>>(f0, f1, f2, f3, rois, (float*)d_out);
}

// round 10
// speedup vs baseline: 1.7260x; 1.0417x over previous
#include <cuda_runtime.h>

// RoIAlign (FPN, 4 levels) + fused 2x2 stride-1 avg epilogue.
// Grid: 4 blocks per roi (channel slices of 64), 256 thr = 8 warps/block.
// Each warp owns 8 channels. Loop order: OUTER over the 7 pooled rows (py),
// INNER unrolled over the 8 channels -> the y-descriptors (smem) are read
// once per py and reused by 8 channels (LDS/channel ~1.75 vs 14), and each
// py issues 24-32 independent gathers before any reduction (deep MLP).
// Lane l (<28) owns x-tap column l = 2*t + k. Fast path (rh <= 14 px):
// each pooled row's 4 bilinear rows fit a 3-row window -> <=3 loads.
// Epilogue: out[py-1,px] = sum over lanes 4px..4px+7 of
// (v[py-1]+v[py])*wcol, built by shfl_down 1,2,4 (overlap OK).

namespace {
constexpr int C = 256;

__global__ __launch_bounds__(256, 4)
void roialign_kernel(const float* __restrict__ f0, const float* __restrict__ f1,
                     const float* __restrict__ f2, const float* __restrict__ f3,
                     const float* __restrict__ rois, float* __restrict__ out)
{
    const int roi   = blockIdx.x >> 2;
    const int slice = blockIdx.x & 3;       // 64-channel slice
    const int b = roi >> 9;                 // N = 512
    const float* r = rois + roi * 7;

    __shared__ int    scol[32];             // column index per lane (clamped)
    __shared__ float  swx[32];              // x-weight per lane (0 if invalid)
    __shared__ float4 sy[14];               // {off0, off1 (int bits), wy0, wy1}
    __shared__ float4 spy[7];               // fast: {baseOff bits, w0, w1, w2}

    const int tid = threadIdx.x;
    const int lev = (int)r[6];
    const int Wd = 160 >> lev;
    const float scale = 8.0f / (float)(1 << lev);

    // uniform fast-path condition: sample stride rh/14 <= 1
    const float rh_u = fmaxf((r[4] - r[2]) * scale, 1.0f);
    const bool fast = (rh_u <= 14.0f);

    if (tid < 32) {                         // x-tap setup: lane l = 2*t + k
        int l = min(tid, 27);               // idle lanes alias lane 27
        int t = l >> 1, k = l & 1;
        const float c1 = r[1] * scale;
        const float c2 = r[3] * scale;
        const float bin = fmaxf(c2 - c1, 1.0f) * (1.0f / 7.0f);
        const float off = (float)(t >> 1) + ((t & 1) ? 0.75f : 0.25f);
        const float pos = c1 + off * bin;
        const bool valid = (pos >= -1.0f) && (pos <= (float)Wd);
        const float p = fminf(fmaxf(pos, 0.0f), (float)(Wd - 1));
        const float p0 = floorf(p);
        const int i0 = (int)p0;
        const int i1 = min(i0 + 1, Wd - 1);
        const float lx = p - p0;
        scol[tid] = k ? i1 : i0;
        // fold the 2x2-avg-pool scale (1/16) into the x weight
        swx[tid] = (tid < 28 && valid) ? 0.0625f * (k ? lx : 1.0f - lx) : 0.0f;
    } else if (tid < 46) {                  // y-sample setup: s = tid - 32
        const int s = tid - 32;
        const float c1 = r[2] * scale;
        const float c2 = r[4] * scale;
        const float bin = fmaxf(c2 - c1, 1.0f) * (1.0f / 7.0f);
        const float off = (float)(s >> 1) + ((s & 1) ? 0.75f : 0.25f);
        const float pos = c1 + off * bin;
        const bool valid = (pos >= -1.0f) && (pos <= (float)Wd);
        const float p = fminf(fmaxf(pos, 0.0f), (float)(Wd - 1));
        const float p0 = floorf(p);
        const int i0 = (int)p0;
        const int i1 = min(i0 + 1, Wd - 1);
        const float ly = p - p0;
        float4 v;
        v.x = __int_as_float(i0 * Wd);
        v.y = __int_as_float(i1 * Wd);
        v.z = valid ? (1.0f - ly) : 0.0f;
        v.w = valid ? ly : 0.0f;
        sy[s] = v;
    } else if (tid < 53 && fast) {          // fast-path 3-row windows, py = tid-46
        const int py = tid - 46;
        const float c1 = r[2] * scale;
        const float c2 = r[4] * scale;
        const float bin = fmaxf(c2 - c1, 1.0f) * (1.0f / 7.0f);
        float w[3] = {0.0f, 0.0f, 0.0f};
        int base = 0;
        #pragma unroll
        for (int h = 0; h < 2; ++h) {
            const int s = 2 * py + h;
            const float off = (float)(s >> 1) + ((s & 1) ? 0.75f : 0.25f);
            const float pos = c1 + off * bin;
            const bool valid = (pos >= -1.0f) && (pos <= (float)Wd);
            const float p = fminf(fmaxf(pos, 0.0f), (float)(Wd - 1));
            const float p0 = floorf(p);
            const int i0 = (int)p0;
            const int i1 = min(i0 + 1, Wd - 1);
            const float ly = p - p0;
            if (h == 0) base = i0;          // rows monotone within the bin
            w[i0 - base] += valid ? (1.0f - ly) : 0.0f;
            w[i1 - base] += valid ? ly : 0.0f;
        }
        float4 e;
        e.x = __int_as_float(base * Wd);
        e.y = w[0]; e.z = w[1]; e.w = w[2];
        spy[py] = e;
    }
    __syncthreads();

    const float* fb = (lev == 0) ? f0 : (lev == 1) ? f1 : (lev == 2) ? f2 : f3;
    const int HW = Wd * Wd;
    const int warp = tid >> 5;
    const int lane = tid & 31;

    const int mycol = scol[lane];
    const float wcol = swx[lane];
    const bool active = (lane & 3) == 0 && lane < 24;
    const int px = lane >> 2;               // 0..5 when active
    const int cbase = slice * 64 + warp * 8;
    const float* fc0 = fb + (size_t)(b * C + cbase) * HW + mycol;
    float* op0 = out + (size_t)roi * (C * 36) + cbase * 36 + px;

    float prev[8];
    #pragma unroll 1
    for (int py = 0; py < 7; ++py) {
        float v[8];
        if (fast) {
            const float4 e = spy[py];
            const int bo = __float_as_int(e.x);
            const bool h0 = (e.y != 0.0f);
            const bool h1 = (e.z != 0.0f);
            const bool h2 = (e.w != 0.0f);
            #pragma unroll
            for (int ch = 0; ch < 8; ++ch) {
                const float* fc = fc0 + ch * HW;
                float a = 0.0f;
                if (h0) a += e.y * __ldg(fc + bo);
                if (h1) a += e.z * __ldg(fc + bo + Wd);
                if (h2) a += e.w * __ldg(fc + bo + 2 * Wd);
                v[ch] = a;
            }
        } else {
            const float4 y0 = sy[2 * py];
            const float4 y1 = sy[2 * py + 1];
            const int o00 = __float_as_int(y0.x);
            const int o01 = __float_as_int(y0.y);
            const int o10 = __float_as_int(y1.x);
            const int o11 = __float_as_int(y1.y);
            #pragma unroll
            for (int ch = 0; ch < 8; ++ch) {
                const float* fc = fc0 + ch * HW;
                const float a00 = __ldg(fc + o00);
                const float a01 = __ldg(fc + o01);
                const float a10 = __ldg(fc + o10);
                const float a11 = __ldg(fc + o11);
                v[ch] = y0.z * a00 + y0.w * a01 + y1.z * a10 + y1.w * a11;
            }
        }
        if (py > 0) {
            #pragma unroll
            for (int ch = 0; ch < 8; ++ch) {
                float u = (prev[ch] + v[ch]) * wcol;
                u += __shfl_down_sync(0xFFFFFFFFu, u, 1);
                u += __shfl_down_sync(0xFFFFFFFFu, u, 2);
                u += __shfl_down_sync(0xFFFFFFFFu, u, 4);
                if (active)
                    op0[ch * 36 + (py - 1) * 6] = u;
            }
        }
        #pragma unroll
        for (int ch = 0; ch < 8; ++ch) prev[ch] = v[ch];
    }
}
} // namespace

extern "C" void kernel_launch(void* const* d_in, const int* in_sizes, int n_in,
                              void* d_out, int out_size) {
    const float* f0   = (const float*)d_in[0];
    const float* f1   = (const float*)d_in[1];
    const float* f2   = (const float*)d_in[2];
    const float* f3   = (const float*)d_in[3];
    const float* rois = (const float*)d_in[4];
    const int nroi = in_sizes[4] / 7;       // B*N = 1024
    roialign_kernel<<<nroi * 4, 256>>>(f0, f1, f2, f3, rois, (float*)d_out);
}